// round 1
// baseline (speedup 1.0000x reference)
#include <cuda_runtime.h>
#include <cuda_bf16.h>

#define DT 0.02f
#define NSUB 10

// RK45 (Dormand–Prince) coefficients, rounded to f32 exactly as JAX does
// (python float -> f32 multiply against f32 arrays).
__device__ __forceinline__ float C(double x) { return (float)x; }

struct Accel {
    float tfr, tfi, drag, lift;
    __device__ __forceinline__ void eval(float vr, float vi, float& ar, float& ai) const {
        float x = fmaf(vr, vr, vi * vi);
        float s = x * rsqrtf(x);           // |v| via 1 MUFU + 1 mul (~2 ulp)
        float ds = drag * s;
        float ls = lift * s;
        ar = fmaf(-ds, vr, tfr);
        ar = fmaf(-ls, vi, ar);
        ai = fmaf(-ds, vi, tfi);
        ai = fmaf( ls, vr, ai);
    }
};

__global__ __launch_bounds__(256)
void ship_physics_kernel(
    const int*   __restrict__ actions,     // [N,5]
    const float* __restrict__ pos_r_in,
    const float* __restrict__ pos_i_in,
    const float* __restrict__ vel_r_in,
    const float* __restrict__ vel_i_in,
    const float* __restrict__ turn_offset_in,
    const float* __restrict__ boost_in,
    const float* __restrict__ max_boost_in,
    const float* __restrict__ thrust_in,
    const float* __restrict__ turn_table,   // [8]
    const float* __restrict__ energy_table, // [4]
    const float* __restrict__ drag_table,   // [4]
    const float* __restrict__ lift_table,   // [2]
    const float* __restrict__ thrust_table, // [4]
    float* __restrict__ out,                // [8, N]
    int n)
{
    int i = blockIdx.x * blockDim.x + threadIdx.x;
    if (i >= n) return;

    // ---- action decode ----
    const int* arow = actions + (size_t)i * 5;
    int a0 = arow[0], a1 = arow[1], a2 = arow[2], a3 = arow[3], a4 = arow[4];
    bool left  = a0 > 0;
    bool right = a1 > 0;
    int sharp  = a4;
    int idx_turn = a0 + 2 * a1 + 4 * sharp;
    int idx_fb   = a2 + 2 * a3;

    float turn_angle = __ldg(turn_table + idx_turn);
    float to = (left && right) ? turn_offset_in[i] : turn_angle;
    float co, si;
    sincosf(to, &si, &co);

    float vr = vel_r_in[i];
    float vi = vel_i_in[i];

    // ---- boost / thrust ----
    float cost = __ldg(energy_table + idx_fb);
    float boost = boost_in[i] - cost * DT;
    float mb = max_boost_in[i];
    boost = fminf(fmaxf(boost, 0.0f), mb);
    float tm = __ldg(thrust_table + idx_fb);
    if (!(boost > 0.0f)) tm = 1.0f;

    // initial attitude (thrust direction)
    {
        float x0 = fmaf(vr, vr, vi * vi);
        float inv0 = rsqrtf(x0);
        float dr = vr * inv0, di = vi * inv0;
        float attr = dr * co - di * si;
        float atti = dr * si + di * co;
        float th = thrust_in[i] * tm;
        // stash into registers via struct below
        float tfr = th * attr;
        float tfi = th * atti;

        int turning = (left || right) ? 1 : 0;
        float drag = __ldg(drag_table + (turning + 2 * sharp));
        float base_lift = __ldg(lift_table + sharp);
        float turn_dir = (float)(right ? 1 : 0) - (float)(left ? 1 : 0);
        float lift = (left != right) ? turn_dir * base_lift : 0.0f;

        Accel A{tfr, tfi, drag, lift};

        float pr = pos_r_in[i];
        float pi = pos_i_in[i];

        const float h = C(0.02 / 10.0);
        // stage coefficients (f32)
        const float A21 = C(1.0/5.0);
        const float A31 = C(3.0/40.0),      A32 = C(9.0/40.0);
        const float A41 = C(44.0/45.0),     A42 = C(-56.0/15.0),   A43 = C(32.0/9.0);
        const float A51 = C(19372.0/6561.0),A52 = C(-25360.0/2187.0),A53 = C(64448.0/6561.0),A54 = C(-212.0/729.0);
        const float A61 = C(9017.0/3168.0), A62 = C(-355.0/33.0),  A63 = C(46732.0/5247.0), A64 = C(49.0/176.0), A65 = C(-5103.0/18656.0);
        const float B1  = C(35.0/384.0),    B3  = C(500.0/1113.0), B4  = C(125.0/192.0),    B5  = C(-2187.0/6784.0), B6 = C(11.0/84.0);

        #pragma unroll 2
        for (int step = 0; step < NSUB; ++step) {
            float a1r, a1i, a2r, a2i, a3r, a3i, a4r, a4i, a5r, a5i, a6r, a6i;

            A.eval(vr, vi, a1r, a1i);

            float v2r = fmaf(h, A21 * a1r, vr);
            float v2i = fmaf(h, A21 * a1i, vi);
            A.eval(v2r, v2i, a2r, a2i);

            float tr = fmaf(A32, a2r, A31 * a1r);
            float ti = fmaf(A32, a2i, A31 * a1i);
            float v3r = fmaf(h, tr, vr);
            float v3i = fmaf(h, ti, vi);
            A.eval(v3r, v3i, a3r, a3i);

            tr = fmaf(A43, a3r, fmaf(A42, a2r, A41 * a1r));
            ti = fmaf(A43, a3i, fmaf(A42, a2i, A41 * a1i));
            float v4r = fmaf(h, tr, vr);
            float v4i = fmaf(h, ti, vi);
            A.eval(v4r, v4i, a4r, a4i);

            tr = fmaf(A54, a4r, fmaf(A53, a3r, fmaf(A52, a2r, A51 * a1r)));
            ti = fmaf(A54, a4i, fmaf(A53, a3i, fmaf(A52, a2i, A51 * a1i)));
            float v5r = fmaf(h, tr, vr);
            float v5i = fmaf(h, ti, vi);
            A.eval(v5r, v5i, a5r, a5i);

            tr = fmaf(A65, a5r, fmaf(A64, a4r, fmaf(A63, a3r, fmaf(A62, a2r, A61 * a1r))));
            ti = fmaf(A65, a5i, fmaf(A64, a4i, fmaf(A63, a3i, fmaf(A62, a2i, A61 * a1i))));
            float v6r = fmaf(h, tr, vr);
            float v6i = fmaf(h, ti, vi);
            A.eval(v6r, v6i, a6r, a6i);

            // position update: k_pos stages are the stage velocities (k1v = v)
            float kpr = fmaf(B6, v6r, fmaf(B5, v5r, fmaf(B4, v4r, fmaf(B3, v3r, B1 * vr))));
            float kpi = fmaf(B6, v6i, fmaf(B5, v5i, fmaf(B4, v4i, fmaf(B3, v3i, B1 * vi))));
            pr = fmaf(h, kpr, pr);
            pi = fmaf(h, kpi, pi);

            // velocity update
            float kvr = fmaf(B6, a6r, fmaf(B5, a5r, fmaf(B4, a4r, fmaf(B3, a3r, B1 * a1r))));
            float kvi = fmaf(B6, a6i, fmaf(B5, a5i, fmaf(B4, a4i, fmaf(B3, a3i, B1 * a1i))));
            vr = fmaf(h, kvr, vr);
            vi = fmaf(h, kvi, vi);
        }

        // ---- final attitude ----
        float x1 = fmaf(vr, vr, vi * vi);
        float inv1 = rsqrtf(x1);
        float dr1 = vr * inv1, di1 = vi * inv1;
        float attr1 = dr1 * co - di1 * si;
        float atti1 = dr1 * si + di1 * co;

        size_t N = (size_t)n;
        out[0 * N + i] = pr;
        out[1 * N + i] = pi;
        out[2 * N + i] = vr;
        out[3 * N + i] = vi;
        out[4 * N + i] = attr1;
        out[5 * N + i] = atti1;
        out[6 * N + i] = boost;
        out[7 * N + i] = to;
    }
}

extern "C" void kernel_launch(void* const* d_in, const int* in_sizes, int n_in,
                              void* d_out, int out_size) {
    const int*   actions      = (const int*)  d_in[0];
    const float* pos_r        = (const float*)d_in[1];
    const float* pos_i        = (const float*)d_in[2];
    const float* vel_r        = (const float*)d_in[3];
    const float* vel_i        = (const float*)d_in[4];
    const float* turn_offset  = (const float*)d_in[5];
    const float* boost        = (const float*)d_in[6];
    const float* max_boost    = (const float*)d_in[7];
    const float* thrust       = (const float*)d_in[8];
    const float* turn_table   = (const float*)d_in[9];
    const float* energy_table = (const float*)d_in[10];
    const float* drag_table   = (const float*)d_in[11];
    const float* lift_table   = (const float*)d_in[12];
    const float* thrust_table = (const float*)d_in[13];

    int n = in_sizes[1];  // pos_r element count = N
    int threads = 256;
    int blocks = (n + threads - 1) / threads;
    ship_physics_kernel<<<blocks, threads>>>(
        actions, pos_r, pos_i, vel_r, vel_i, turn_offset, boost, max_boost, thrust,
        turn_table, energy_table, drag_table, lift_table, thrust_table,
        (float*)d_out, n);
}

// round 2
// speedup vs baseline: 1.1923x; 1.1923x over previous
#include <cuda_runtime.h>
#include <cuda_bf16.h>

#define DT 0.02f
#define NSUB 10

// ---------------- packed f32x2 helpers (Blackwell FFMA2 path) ----------------
typedef unsigned long long u64p;

__device__ __forceinline__ u64p pk2(float lo, float hi) {
    u64p r; asm("mov.b64 %0, {%1, %2};" : "=l"(r) : "f"(lo), "f"(hi)); return r;
}
__device__ __forceinline__ void upk2(u64p v, float& lo, float& hi) {
    asm("mov.b64 {%0, %1}, %2;" : "=f"(lo), "=f"(hi) : "l"(v));
}
__device__ __forceinline__ u64p ffma2(u64p a, u64p b, u64p c) {
    u64p d; asm("fma.rn.f32x2 %0, %1, %2, %3;" : "=l"(d) : "l"(a), "l"(b), "l"(c)); return d;
}
__device__ __forceinline__ u64p fmul2(u64p a, u64p b) {
    u64p d; asm("mul.rn.f32x2 %0, %1, %2;" : "=l"(d) : "l"(a), "l"(b)); return d;
}
__device__ __forceinline__ u64p fadd2(u64p a, u64p b) {
    u64p d; asm("add.rn.f32x2 %0, %1, %2;" : "=l"(d) : "l"(a), "l"(b)); return d;
}
__device__ __forceinline__ float fast_len(float vr, float vi) {
    float x = fmaf(vr, vr, vi * vi);
    float s; asm("sqrt.approx.f32 %0, %1;" : "=f"(s) : "f"(x));
    return s;
}

// acceleration: a = tf - drag*s*v - lift*s*rot90(v), packed over (r,i)
// dn2 = (-drag,-drag), lp2 = (-lift,+lift), tf2 = (tfr,tfi)
__device__ __forceinline__ u64p eval_acc(u64p v, u64p dn2, u64p lp2, u64p tf2) {
    float vr, vi; upk2(v, vr, vi);
    float s = fast_len(vr, vi);
    u64p u = ffma2(lp2, pk2(vi, vr), fmul2(dn2, v));
    return ffma2(pk2(s, s), u, tf2);
}

__device__ __forceinline__ float FC(double x) { return (float)x; }

__global__ __launch_bounds__(256)
void ship_physics_kernel(
    const int*   __restrict__ actions,      // [N,5]
    const float* __restrict__ pos_r_in,
    const float* __restrict__ pos_i_in,
    const float* __restrict__ vel_r_in,
    const float* __restrict__ vel_i_in,
    const float* __restrict__ turn_offset_in,
    const float* __restrict__ boost_in,
    const float* __restrict__ max_boost_in,
    const float* __restrict__ thrust_in,
    const float* __restrict__ turn_table,   // [8]
    const float* __restrict__ energy_table, // [4]
    const float* __restrict__ drag_table,   // [4]
    const float* __restrict__ lift_table,   // [2]
    const float* __restrict__ thrust_table, // [4]
    float* __restrict__ out,                // [8, N]
    int n)
{
    int i = blockIdx.x * blockDim.x + threadIdx.x;
    if (i >= n) return;

    // ---- action decode ----
    const int* arow = actions + (size_t)i * 5;
    int a0 = arow[0], a1 = arow[1], a2c = arow[2], a3c = arow[3], a4c = arow[4];
    bool left  = a0 > 0;
    bool right = a1 > 0;
    int sharp  = a4c;
    int idx_turn = a0 + 2 * a1 + 4 * sharp;
    int idx_fb   = a2c + 2 * a3c;

    float turn_angle = __ldg(turn_table + idx_turn);
    float to = (left && right) ? turn_offset_in[i] : turn_angle;
    float co, si;
    sincosf(to, &si, &co);

    float vr = vel_r_in[i];
    float vi = vel_i_in[i];

    // ---- boost / thrust ----
    float cost = __ldg(energy_table + idx_fb);
    float boost = boost_in[i] - cost * DT;
    float mb = max_boost_in[i];
    boost = fminf(fmaxf(boost, 0.0f), mb);
    float tm = __ldg(thrust_table + idx_fb);
    if (!(boost > 0.0f)) tm = 1.0f;

    // ---- initial attitude / per-thread dynamics params ----
    float x0 = fmaf(vr, vr, vi * vi);
    float inv0 = rsqrtf(x0);
    float dr = vr * inv0, di = vi * inv0;
    float attr = dr * co - di * si;
    float atti = dr * si + di * co;
    float th = thrust_in[i] * tm;
    float tfr = th * attr;
    float tfi = th * atti;

    int turning = (left || right) ? 1 : 0;
    float drag = __ldg(drag_table + (turning + 2 * sharp));
    float base_lift = __ldg(lift_table + sharp);
    float turn_dir = (float)(right ? 1 : 0) - (float)(left ? 1 : 0);
    float lift = (left != right) ? turn_dir * base_lift : 0.0f;

    u64p tf2 = pk2(tfr, tfi);
    u64p dn2 = pk2(-drag, -drag);
    u64p lp2 = pk2(-lift,  lift);

    u64p v = pk2(vr, vi);
    u64p p = pk2(pos_r_in[i], pos_i_in[i]);

    // ---- RK45 coefficients with h folded in ----
    const double H = (double)FC(0.02 / 10.0);
    const float c21 = FC(H * (1.0/5.0));
    const float c31 = FC(H * (3.0/40.0)),       c32 = FC(H * (9.0/40.0));
    const float c41 = FC(H * (44.0/45.0)),      c42 = FC(H * (-56.0/15.0)),     c43 = FC(H * (32.0/9.0));
    const float c51 = FC(H * (19372.0/6561.0)), c52 = FC(H * (-25360.0/2187.0)),c53 = FC(H * (64448.0/6561.0)), c54 = FC(H * (-212.0/729.0));
    const float c61 = FC(H * (9017.0/3168.0)),  c62 = FC(H * (-355.0/33.0)),    c63 = FC(H * (46732.0/5247.0)), c64 = FC(H * (49.0/176.0)), c65 = FC(H * (-5103.0/18656.0));
    const float b1  = FC(H * (35.0/384.0)),     b3  = FC(H * (500.0/1113.0)),   b4  = FC(H * (125.0/192.0)),    b5  = FC(H * (-2187.0/6784.0)), b6 = FC(H * (11.0/84.0));

    const u64p C21 = pk2(c21, c21);
    const u64p C31 = pk2(c31, c31), C32 = pk2(c32, c32);
    const u64p C41 = pk2(c41, c41), C42 = pk2(c42, c42), C43 = pk2(c43, c43);
    const u64p C51 = pk2(c51, c51), C52 = pk2(c52, c52), C53 = pk2(c53, c53), C54 = pk2(c54, c54);
    const u64p C61 = pk2(c61, c61), C62 = pk2(c62, c62), C63 = pk2(c63, c63), C64 = pk2(c64, c64), C65 = pk2(c65, c65);
    const u64p B1  = pk2(b1, b1),   B3  = pk2(b3, b3),   B4  = pk2(b4, b4),   B5  = pk2(b5, b5),   B6  = pk2(b6, b6);

    #pragma unroll 1
    for (int st = 0; st < NSUB; ++st) {
        u64p k1 = eval_acc(v, dn2, lp2, tf2);
        u64p kp = fmul2(B1, v);
        u64p kv = fmul2(B1, k1);

        u64p vs = ffma2(C21, k1, v);
        u64p k2 = eval_acc(vs, dn2, lp2, tf2);

        vs = ffma2(C32, k2, ffma2(C31, k1, v));
        u64p k3 = eval_acc(vs, dn2, lp2, tf2);
        kp = ffma2(B3, vs, kp);
        kv = ffma2(B3, k3, kv);

        vs = ffma2(C43, k3, ffma2(C42, k2, ffma2(C41, k1, v)));
        u64p k4 = eval_acc(vs, dn2, lp2, tf2);
        kp = ffma2(B4, vs, kp);
        kv = ffma2(B4, k4, kv);

        vs = ffma2(C54, k4, ffma2(C53, k3, ffma2(C52, k2, ffma2(C51, k1, v))));
        u64p k5 = eval_acc(vs, dn2, lp2, tf2);
        kp = ffma2(B5, vs, kp);
        kv = ffma2(B5, k5, kv);

        vs = ffma2(C65, k5, ffma2(C64, k4, ffma2(C63, k3, ffma2(C62, k2, ffma2(C61, k1, v)))));
        u64p k6 = eval_acc(vs, dn2, lp2, tf2);
        kp = ffma2(B6, vs, kp);
        kv = ffma2(B6, k6, kv);

        p = fadd2(p, kp);
        v = fadd2(v, kv);
    }

    // ---- final attitude ----
    float pr, pi_, vr1, vi1;
    upk2(p, pr, pi_);
    upk2(v, vr1, vi1);
    float x1 = fmaf(vr1, vr1, vi1 * vi1);
    float inv1 = rsqrtf(x1);
    float dr1 = vr1 * inv1, di1 = vi1 * inv1;
    float attr1 = dr1 * co - di1 * si;
    float atti1 = dr1 * si + di1 * co;

    size_t N = (size_t)n;
    out[0 * N + i] = pr;
    out[1 * N + i] = pi_;
    out[2 * N + i] = vr1;
    out[3 * N + i] = vi1;
    out[4 * N + i] = attr1;
    out[5 * N + i] = atti1;
    out[6 * N + i] = boost;
    out[7 * N + i] = to;
}

extern "C" void kernel_launch(void* const* d_in, const int* in_sizes, int n_in,
                              void* d_out, int out_size) {
    const int*   actions      = (const int*)  d_in[0];
    const float* pos_r        = (const float*)d_in[1];
    const float* pos_i        = (const float*)d_in[2];
    const float* vel_r        = (const float*)d_in[3];
    const float* vel_i        = (const float*)d_in[4];
    const float* turn_offset  = (const float*)d_in[5];
    const float* boost        = (const float*)d_in[6];
    const float* max_boost    = (const float*)d_in[7];
    const float* thrust       = (const float*)d_in[8];
    const float* turn_table   = (const float*)d_in[9];
    const float* energy_table = (const float*)d_in[10];
    const float* drag_table   = (const float*)d_in[11];
    const float* lift_table   = (const float*)d_in[12];
    const float* thrust_table = (const float*)d_in[13];

    int n = in_sizes[1];  // pos_r element count = N
    int threads = 256;
    int blocks = (n + threads - 1) / threads;
    ship_physics_kernel<<<blocks, threads>>>(
        actions, pos_r, pos_i, vel_r, vel_i, turn_offset, boost, max_boost, thrust,
        turn_table, energy_table, drag_table, lift_table, thrust_table,
        (float*)d_out, n);
}